// round 7
// baseline (speedup 1.0000x reference)
#include <cuda_runtime.h>
#include <cstdint>

typedef unsigned long long u64;
typedef ulonglong2 u64x2;

#define HD   19      // hidden size
#define HP   10      // hidden pairs (padded to 20)
#define WPAD 12      // u64 per packed weight row (10 used; 96B, 16B-aligned)
#define DD   64      // input size
#define TPB  128
#define RPT  4       // batch rows per thread
#define RPB  (TPB * RPT)   // 512 rows per block
#define NPART 1024

__device__ float g_partials[NPART];

struct Tables {
    u64 Wi2[DD * WPAD];   // [k][jp]: (Wi[2jp][k], Wi[2jp+1][k])
    u64 Wr2[HD * WPAD];
    u64 Wo2[HD * WPAD];
    u64 bi2[HP];
    u64 bo2[HP];
    u64 bdt2[HP];         // packed dt/tau_dyn, pad lane = 0
};
__device__ Tables g_tab;
#define TAB_U64 ((int)(sizeof(Tables) / 8))     // 1254
#define MST_U64 (RPB * HP)                      // 5120
#define SM_U64  (TAB_U64 + MST_U64)             // 6374
#define SM_BYTES (SM_U64 * 8)                   // 50992

// ---------- packed f32x2 helpers (sm_103a) ----------
static __device__ __forceinline__ u64 pk2(float lo, float hi) {
    u64 r; asm("mov.b64 %0,{%1,%2};" : "=l"(r) : "f"(lo), "f"(hi)); return r;
}
static __device__ __forceinline__ void upk2(u64 v, float& lo, float& hi) {
    asm("mov.b64 {%0,%1},%2;" : "=f"(lo), "=f"(hi) : "l"(v));
}
static __device__ __forceinline__ u64 fma2(u64 a, u64 b, u64 c) {
    u64 d; asm("fma.rn.f32x2 %0,%1,%2,%3;" : "=l"(d) : "l"(a), "l"(b), "l"(c)); return d;
}
static __device__ __forceinline__ float tanha(float v) {
    float r; asm("tanh.approx.f32 %0,%1;" : "=f"(r) : "f"(v)); return r;
}

// ---------- kernel 1: per-block partial sums of |x| ----------
__global__ void __launch_bounds__(256) k_partial(const float4* __restrict__ x, int n4) {
    float s = 0.f;
    for (int i = blockIdx.x * blockDim.x + threadIdx.x; i < n4;
         i += gridDim.x * blockDim.x) {
        float4 v = x[i];
        s += fabsf(v.x) + fabsf(v.y) + fabsf(v.z) + fabsf(v.w);
    }
#pragma unroll
    for (int o = 16; o > 0; o >>= 1) s += __shfl_down_sync(0xffffffffu, s, o);
    __shared__ float ws[8];
    int w = threadIdx.x >> 5, l = threadIdx.x & 31;
    if (l == 0) ws[w] = s;
    __syncthreads();
    if (threadIdx.x == 0) {
        float t = 0.f;
#pragma unroll
        for (int i = 0; i < 8; i++) t += ws[i];
        g_partials[blockIdx.x] = t;
    }
}

// ---------- kernel 2: finish reduction + build all packed tables ----------
__global__ void __launch_bounds__(256) k_prep(
    const float* __restrict__ Wi, const float* __restrict__ bi,
    const float* __restrict__ Wr, const float* __restrict__ Wo,
    const float* __restrict__ bo, const float* __restrict__ tau,
    const float* __restrict__ ta, float invN)
{
    __shared__ float red[256];
    __shared__ float urg_s;
    int t = threadIdx.x;

    float s = 0.f;
    for (int i = t; i < NPART; i += 256) s += g_partials[i];
    red[t] = s;
    __syncthreads();
#pragma unroll
    for (int o = 128; o > 0; o >>= 1) {
        if (t < o) red[t] += red[t + o];
        __syncthreads();
    }
    if (t == 0) urg_s = fmaxf(red[0] * invN, 0.01f);
    __syncthreads();
    float urg = urg_s;

    for (int i = t; i < DD * HP; i += 256) {
        int k = i / HP, jp = i % HP;
        float w0 = Wi[(2 * jp) * DD + k];
        float w1 = (2 * jp + 1 < HD) ? Wi[(2 * jp + 1) * DD + k] : 0.f;
        g_tab.Wi2[k * WPAD + jp] = pk2(w0, w1);
        if (jp == 0) {   // zero the pad slots
            g_tab.Wi2[k * WPAD + 10] = 0ull;
            g_tab.Wi2[k * WPAD + 11] = 0ull;
        }
    }
    for (int i = t; i < HD * HP; i += 256) {
        int k = i / HP, jp = i % HP;
        float r0 = Wr[(2 * jp) * HD + k];
        float r1 = (2 * jp + 1 < HD) ? Wr[(2 * jp + 1) * HD + k] : 0.f;
        g_tab.Wr2[k * WPAD + jp] = pk2(r0, r1);
        float o0 = Wo[(2 * jp) * HD + k];
        float o1 = (2 * jp + 1 < HD) ? Wo[(2 * jp + 1) * HD + k] : 0.f;
        g_tab.Wo2[k * WPAD + jp] = pk2(o0, o1);
        if (jp == 0) {
            g_tab.Wr2[k * WPAD + 10] = 0ull; g_tab.Wr2[k * WPAD + 11] = 0ull;
            g_tab.Wo2[k * WPAD + 10] = 0ull; g_tab.Wo2[k * WPAD + 11] = 0ull;
        }
    }
    if (t < HP) {
        float b0 = bi[2 * t];
        float b1 = (2 * t + 1 < HD) ? bi[2 * t + 1] : 0.f;
        g_tab.bi2[t] = pk2(b0, b1);
        float c0 = bo[2 * t];
        float c1 = (2 * t + 1 < HD) ? bo[2 * t + 1] : 0.f;
        g_tab.bo2[t] = pk2(c0, c1);

        float bd0, bd1 = 0.f;
        {
            float td = tau[2 * t] * (1.0f - ta[2 * t]) + ta[2 * t] / urg;
            td = fminf(fmaxf(td, 0.01f), 10.0f);
            bd0 = 0.01f / td;
        }
        if (2 * t + 1 < HD) {
            float td = tau[2 * t + 1] * (1.0f - ta[2 * t + 1]) + ta[2 * t + 1] / urg;
            td = fminf(fmaxf(td, 0.01f), 10.0f);
            bd1 = 0.01f / td;
        }
        g_tab.bdt2[t] = pk2(bd0, bd1);
    }
}

// ---------- kernel 3: fused mapped + recurrence + output, 4 rows/thread ----------
__global__ void __launch_bounds__(TPB)
k_main(const float* __restrict__ x, const int* __restrict__ steps_p,
       float* __restrict__ out, float* __restrict__ hout)
{
    extern __shared__ __align__(16) u64 sm[];   // SM_BYTES
    const int tid = threadIdx.x;

    {   // stage tables
        const u64* gt = (const u64*)&g_tab;
        for (int i = tid; i < TAB_U64; i += TPB) sm[i] = gt[i];
    }
    __syncthreads();
    const u64* sWi = sm;                        // @0     (768)
    const u64* sWr = sWi + DD * WPAD;           // @768   (228)
    const u64* sWo = sWr + HD * WPAD;           // @996   (228)
    const u64* sBi = sWo + HD * WPAD;           // @1224  (10)
    const u64* sBo = sBi + HP;                  // @1234  (10)
    const u64* sBd = sBo + HP;                  // @1244  (10)
    u64* mst = sm + TAB_U64;                    // @1254  (5120)
    // mstage layout: mst[(p*RPT + r)*TPB + tid]

    // ---- phase 1: mapped = x @ Wi^T + bi, per row sequentially ----
    for (int r = 0; r < RPT; r++) {
        const float4* xr = (const float4*)(x +
            ((size_t)blockIdx.x * RPB + r * TPB + tid) * DD);
        u64 m[HP];
#pragma unroll
        for (int p = 0; p < HP; p++) m[p] = sBi[p];
#pragma unroll 4
        for (int q = 0; q < DD / 4; q++) {
            float4 v = xr[q];
            float vv[4] = {v.x, v.y, v.z, v.w};
#pragma unroll
            for (int e = 0; e < 4; e++) {
                u64 xd = pk2(vv[e], vv[e]);
                const u64x2* w = (const u64x2*)&sWi[(q * 4 + e) * WPAD];
#pragma unroll
                for (int p5 = 0; p5 < 5; p5++) {
                    u64x2 ww = w[p5];
                    m[2 * p5]     = fma2(xd, ww.x, m[2 * p5]);
                    m[2 * p5 + 1] = fma2(xd, ww.y, m[2 * p5 + 1]);
                }
            }
        }
#pragma unroll
        for (int p = 0; p < HP; p++) mst[(p * RPT + r) * TPB + tid] = m[p];
    }
    __syncthreads();

    // ---- phase 2: recurrence, 4 rows, h packed over hidden pairs ----
    u64 h[RPT][HP];
    const u64 zero2 = pk2(0.f, 0.f);
    const u64 neg1  = pk2(-1.f, -1.f);
#pragma unroll
    for (int r = 0; r < RPT; r++)
#pragma unroll
        for (int p = 0; p < HP; p++) h[r][p] = zero2;

    const int steps = *steps_p;
    for (int s = 0; s < steps; s++) {
        u64 a[RPT][HP];
#pragma unroll
        for (int p = 0; p < HP; p++)
#pragma unroll
            for (int r = 0; r < RPT; r++)
                a[r][p] = mst[(p * RPT + r) * TPB + tid];

#pragma unroll
        for (int k = 0; k < HD; k++) {
            // broadcast h[.][k] into dup pairs
            u64 d[RPT];
#pragma unroll
            for (int r = 0; r < RPT; r++) {
                float lo, hi;
                upk2(h[r][k >> 1], lo, hi);
                float hv = (k & 1) ? hi : lo;
                d[r] = pk2(hv, hv);
            }
            const u64x2* w = (const u64x2*)&sWr[k * WPAD];
#pragma unroll
            for (int p5 = 0; p5 < 5; p5++) {
                u64x2 ww = w[p5];
#pragma unroll
                for (int r = 0; r < RPT; r++) {
                    a[r][2 * p5]     = fma2(d[r], ww.x, a[r][2 * p5]);
                    a[r][2 * p5 + 1] = fma2(d[r], ww.y, a[r][2 * p5 + 1]);
                }
            }
        }

        // h += b * (tanh(a) - h); b reloaded from smem (broadcast)
#pragma unroll
        for (int p = 0; p < HP; p++) {
            u64 bbp = sBd[p];
#pragma unroll
            for (int r = 0; r < RPT; r++) {
                float u, v;
                upk2(a[r][p], u, v);
                u64 act = pk2(tanha(u), tanha(v));
                u64 dlt = fma2(h[r][p], neg1, act);
                h[r][p] = fma2(bbp, dlt, h[r][p]);
            }
        }
    }

    // ---- phase 3a: out = h @ Wo^T + bo, stage + store ----
    __syncthreads();                 // tables Wi region reused? no — mst reused
    float* f = (float*)mst;          // 10240 floats available, need 9728
    for (int r = 0; r < RPT; r++) {
        u64 o[HP];
#pragma unroll
        for (int p = 0; p < HP; p++) o[p] = sBo[p];
#pragma unroll
        for (int k = 0; k < HD; k++) {
            float lo, hi;
            upk2(h[r][k >> 1], lo, hi);
            float hv = (k & 1) ? hi : lo;
            u64 dk = pk2(hv, hv);
            const u64x2* w = (const u64x2*)&sWo[k * WPAD];
#pragma unroll
            for (int p5 = 0; p5 < 5; p5++) {
                u64x2 ww = w[p5];
                o[2 * p5]     = fma2(dk, ww.x, o[2 * p5]);
                o[2 * p5 + 1] = fma2(dk, ww.y, o[2 * p5 + 1]);
            }
        }
        const int base = (r * TPB + tid) * HD;
#pragma unroll
        for (int p = 0; p < HP; p++) {
            float lo, hi;
            upk2(o[p], lo, hi);
            f[base + 2 * p] = lo;
            if (p < HP - 1) f[base + 2 * p + 1] = hi;
        }
    }
    __syncthreads();
    {
        float4* go = (float4*)(out + (size_t)blockIdx.x * (RPB * HD));
        const float4* f4 = (const float4*)f;
        for (int i = tid; i < RPB * HD / 4; i += TPB) go[i] = f4[i];
    }

    // ---- phase 3b: stage + store h ----
    if (hout) {
        __syncthreads();
        for (int r = 0; r < RPT; r++) {
            const int base = (r * TPB + tid) * HD;
#pragma unroll
            for (int p = 0; p < HP; p++) {
                float lo, hi;
                upk2(h[r][p], lo, hi);
                f[base + 2 * p] = lo;
                if (p < HP - 1) f[base + 2 * p + 1] = hi;
            }
        }
        __syncthreads();
        float4* gh = (float4*)(hout + (size_t)blockIdx.x * (RPB * HD));
        const float4* f4 = (const float4*)f;
        for (int i = tid; i < RPB * HD / 4; i += TPB) gh[i] = f4[i];
    }
}

extern "C" void kernel_launch(void* const* d_in, const int* in_sizes, int n_in,
                              void* d_out, int out_size) {
    const float* x   = (const float*)d_in[0];
    const float* Wi  = (const float*)d_in[1];
    const float* bi  = (const float*)d_in[2];
    const float* Wr  = (const float*)d_in[3];
    const float* Wo  = (const float*)d_in[4];
    const float* bo  = (const float*)d_in[5];
    const float* tau = (const float*)d_in[6];
    const float* ta  = (const float*)d_in[7];
    const int* steps = (const int*)d_in[8];

    const int nx = in_sizes[0];
    const int B  = nx / DD;

    float* out = (float*)d_out;
    long long bh = (long long)B * HD;
    float* hout = ((long long)out_size >= 2 * bh) ? (out + bh) : nullptr;

    static int smem_set = 0;
    if (!smem_set) {
        cudaFuncSetAttribute(k_main, cudaFuncAttributeMaxDynamicSharedMemorySize,
                             SM_BYTES);
        smem_set = 1;
    }

    k_partial<<<NPART, 256>>>((const float4*)x, nx / 4);
    k_prep<<<1, 256>>>(Wi, bi, Wr, Wo, bo, tau, ta, 1.0f / (float)nx);
    k_main<<<B / RPB, TPB, SM_BYTES>>>(x, steps, out, hout);
}